// round 4
// baseline (speedup 1.0000x reference)
#include <cuda_runtime.h>
#include <cuda_bf16.h>

#define BDIM   8
#define SDIM   4096
#define HDIM   16
#define PDIM   64
#define NDIM   64
#define LCHUNK 64
#define NCHUNK 64
#define NBH    (BDIM * HDIM)   // 128
#define SPLIT  4               // chunk-parallel blocks per (b,h)
#define THRESH 14.0f           // exp(-14)=8e-7; truncation ~1e-5 rel << 1e-3

// Scratch (allocation-free rule: __device__ globals)
__device__ float g_w[NBH * SDIM];                      // per-t decay weights
__device__ int   g_start[NBH];                         // first active chunk
__device__ float g_part[SPLIT * NBH * PDIM * NDIM];    // partial sums (8MB)
__device__ int   g_cnt[NBH];                           // completion counters

// Packed-f32 FMA helpers (sm_100+: fma.rn.f32x2)
__device__ __forceinline__ void ffma2(unsigned long long& d,
                                      unsigned long long a,
                                      unsigned long long b) {
    asm("fma.rn.f32x2 %0, %1, %2, %0;" : "+l"(d) : "l"(a), "l"(b));
}
__device__ __forceinline__ unsigned long long pack2(float lo, float hi) {
    unsigned long long r;
    asm("mov.b64 %0, {%1, %2};" : "=l"(r) : "f"(lo), "f"(hi));
    return r;
}
__device__ __forceinline__ void unpack2(unsigned long long v, float& lo, float& hi) {
    asm("mov.b64 {%0, %1}, %2;" : "=f"(lo), "=f"(hi) : "l"(v));
}

union F4U2 { float4 f4; unsigned long long u2[2]; };

// ---------------------------------------------------------------------------
// Prep: grid NBH x 512 threads. Chunk totals (8 thr/chunk, consecutive-t
// loads), suffix scan (warp 0), weights via per-warp pair-scan (16 warps).
// Also resets g_cnt for this graph replay.
// ---------------------------------------------------------------------------
__global__ void __launch_bounds__(512) prep_kernel(const float* __restrict__ A) {
    const int bh   = blockIdx.x;
    const int b    = bh >> 4;
    const int h    = bh & 15;
    const int tid  = threadIdx.x;
    const int lane = tid & 31;
    const int warp = tid >> 5;

    __shared__ float Tj[NCHUNK];
    __shared__ float Uj[NCHUNK];
    __shared__ int   s_start;

    const float* Ab = A + (long)b * SDIM * HDIM + h;

    if (tid == 0) { s_start = NCHUNK - 1; g_cnt[bh] = 0; }

    // Phase 1: chunk totals, 8 threads per chunk, 8 consecutive t each
    {
        const int j = tid >> 3, q = tid & 7;
        const int t0 = j * LCHUNK + q * 8;
        float s = 0.0f;
        #pragma unroll
        for (int i = 0; i < 8; i++) s += Ab[(t0 + i) * HDIM];
        s += __shfl_down_sync(0xffffffffu, s, 4);
        s += __shfl_down_sync(0xffffffffu, s, 2);
        s += __shfl_down_sync(0xffffffffu, s, 1);
        if (q == 0) Tj[j] = s;
    }
    __syncthreads();

    // Phase 2: suffix sums via reversed inclusive warp scan (warp 0)
    if (warp == 0) {
        const int r0 = 2 * lane, r1 = 2 * lane + 1;
        const float a0 = Tj[63 - r0];
        const float a1 = Tj[63 - r1];
        float sc = a0 + a1;
        #pragma unroll
        for (int d = 1; d < 32; d <<= 1) {
            float o = __shfl_up_sync(0xffffffffu, sc, d);
            if (lane >= d) sc += o;
        }
        const float P1 = sc;
        const float P0 = sc - a1;
        Uj[63 - r0] = P0 - a0;
        Uj[63 - r1] = P1 - a1;
    }
    __syncthreads();

    if (tid < NCHUNK && Uj[tid] > -THRESH) atomicMin(&s_start, tid);
    __syncthreads();
    const int start = s_start;
    if (tid == 0) g_start[bh] = start;

    // Phase 3: weights for active chunks, one warp per chunk (16 warps)
    for (int j = start + warp; j < NCHUNK; j += 16) {
        const int t0 = j * LCHUNK;
        const float a0 = Ab[(t0 + 2 * lane)     * HDIM];
        const float a1 = Ab[(t0 + 2 * lane + 1) * HDIM];
        float sc = a0 + a1;
        #pragma unroll
        for (int d = 1; d < 32; d <<= 1) {
            float o = __shfl_up_sync(0xffffffffu, sc, d);
            if (lane >= d) sc += o;
        }
        const float cs1 = sc;
        const float cs0 = sc - a1;
        const float base = Uj[j] + Tj[j];
        float2 wv;
        wv.x = __expf(base - cs0);
        wv.y = __expf(base - cs1);
        ((float2*)(g_w + bh * SDIM + t0))[lane] = wv;
    }
}

// ---------------------------------------------------------------------------
// Main: grid (NBH, SPLIT), 128 threads (4 warps -> all 4 SMSPs).
// 8p x 4n register tile per thread, packed FFMA2 over p-pairs.
// Last split block per bh reduces the partials (deterministic k-order).
// ---------------------------------------------------------------------------
__global__ void __launch_bounds__(128)
mamba_state_kernel(const float* __restrict__ X,
                   const float* __restrict__ B,
                   float* __restrict__ out) {
    __shared__ float xs[LCHUNK][PDIM];   // w-scaled X tile [l][p]
    __shared__ float bs[LCHUNK][NDIM];   // B tile [l][n]
    __shared__ int   s_done;

    const int bh  = blockIdx.x;
    const int k0  = blockIdx.y;
    const int b   = bh >> 4;
    const int h   = bh & 15;
    const int tid = threadIdx.x;
    const int tp  = tid >> 4;            // 0..7  : p-group of 8 rows
    const int tn  = tid & 15;            // 0..15 : n-group of 4 cols

    const int j0 = g_start[bh];

    const float4* X4 = (const float4*)X;
    const float4* B4 = (const float4*)B;
    const float*  wrow = g_w + bh * SDIM;

    // acc2[pi][n]: (out[tp*8+2pi, tn*4+n], out[tp*8+2pi+1, tn*4+n])
    unsigned long long acc2[4][4];
    #pragma unroll
    for (int i = 0; i < 4; i++)
        #pragma unroll
        for (int n = 0; n < 4; n++) acc2[i][n] = 0ull;

    for (int j = j0 + k0; j < NCHUNK; j += SPLIT) {
        const int t0 = j * LCHUNK;
        // Load tile: 1024 float4 each for x and b, 8 per thread, coalesced
        #pragma unroll
        for (int k = 0; k < 8; k++) {
            const int idx = k * 128 + tid;
            const int row = idx >> 4;
            const int col = idx & 15;
            const int t   = t0 + row;
            const int base = ((b * SDIM + t) * HDIM + h) * 16 + col;
            float4 xv = X4[base];
            const float4 bv = B4[base];
            const float w = wrow[t];
            xv.x *= w; xv.y *= w; xv.z *= w; xv.w *= w;
            *(float4*)&xs[row][col * 4] = xv;
            *(float4*)&bs[row][col * 4] = bv;
        }
        __syncthreads();

        #pragma unroll 2
        for (int l = 0; l < LCHUNK; l++) {
            F4U2 xa, xb, bv;
            xa.f4 = *(const float4*)&xs[l][tp * 8];
            xb.f4 = *(const float4*)&xs[l][tp * 8 + 4];
            bv.f4 = *(const float4*)&bs[l][tn * 4];
            unsigned long long bd[4];
            bd[0] = pack2(bv.f4.x, bv.f4.x);
            bd[1] = pack2(bv.f4.y, bv.f4.y);
            bd[2] = pack2(bv.f4.z, bv.f4.z);
            bd[3] = pack2(bv.f4.w, bv.f4.w);
            #pragma unroll
            for (int n = 0; n < 4; n++) {
                ffma2(acc2[0][n], xa.u2[0], bd[n]);
                ffma2(acc2[1][n], xa.u2[1], bd[n]);
                ffma2(acc2[2][n], xb.u2[0], bd[n]);
                ffma2(acc2[3][n], xb.u2[1], bd[n]);
            }
        }
        __syncthreads();
    }

    // Store partial: part[k0][bh][p][n]
    float4* part4 = (float4*)g_part + ((long)k0 * NBH + bh) * PDIM * 16;
    #pragma unroll
    for (int pi = 0; pi < 4; pi++) {
        const int p0 = tp * 8 + 2 * pi;
        float4 v0, v1;
        unpack2(acc2[pi][0], v0.x, v1.x);
        unpack2(acc2[pi][1], v0.y, v1.y);
        unpack2(acc2[pi][2], v0.z, v1.z);
        unpack2(acc2[pi][3], v0.w, v1.w);
        part4[p0 * 16 + tn]       = v0;
        part4[(p0 + 1) * 16 + tn] = v1;
    }

    // Completion protocol: last split block for this bh reduces partials.
    __threadfence();
    __syncthreads();
    if (tid == 0) s_done = atomicAdd(&g_cnt[bh], 1);
    __syncthreads();
    if (s_done == SPLIT - 1) {
        __threadfence();                 // acquire: see peers' partials
        const float4* p4 = (const float4*)g_part;
        float4* out4 = (float4*)out + (long)bh * PDIM * 16;
        const int STRIDE = NBH * PDIM * 16;   // float4 stride between splits
        #pragma unroll
        for (int q = 0; q < 8; q++) {
            const int i = (long)bh * PDIM * 16 + q * 128 + tid;
            float4 s = p4[i];
            #pragma unroll
            for (int k = 1; k < SPLIT; k++) {
                float4 v = p4[i + k * STRIDE];
                s.x += v.x; s.y += v.y; s.z += v.z; s.w += v.w;
            }
            out4[q * 128 + tid] = s;
        }
    }
}

// ---------------------------------------------------------------------------
extern "C" void kernel_launch(void* const* d_in, const int* in_sizes, int n_in,
                              void* d_out, int out_size) {
    const float* X = (const float*)d_in[0];
    const float* A = (const float*)d_in[1];
    const float* B = (const float*)d_in[2];
    float* out = (float*)d_out;

    prep_kernel<<<NBH, 512>>>(A);
    dim3 grid(NBH, SPLIT);
    mamba_state_kernel<<<grid, 128>>>(X, B, out);
}

// round 5
// speedup vs baseline: 1.1604x; 1.1604x over previous
#include <cuda_runtime.h>
#include <cuda_bf16.h>

#define BDIM   8
#define SDIM   4096
#define HDIM   16
#define PDIM   64
#define NDIM   64
#define LCHUNK 64
#define NCHUNK 64
#define NBH    (BDIM * HDIM)   // 128
#define THRESH 14.0f           // exp(-14)=8e-7; truncation ~1e-5 rel << 1e-3

// Packed-f32 FMA helpers (sm_100+: fma.rn.f32x2)
__device__ __forceinline__ void ffma2(unsigned long long& d,
                                      unsigned long long a,
                                      unsigned long long b) {
    asm("fma.rn.f32x2 %0, %1, %2, %0;" : "+l"(d) : "l"(a), "l"(b));
}
__device__ __forceinline__ unsigned long long pack2(float lo, float hi) {
    unsigned long long r;
    asm("mov.b64 %0, {%1, %2};" : "=l"(r) : "f"(lo), "f"(hi));
    return r;
}
__device__ __forceinline__ void unpack2(unsigned long long v, float& lo, float& hi) {
    asm("mov.b64 {%0, %1}, %2;" : "=f"(lo), "=f"(hi) : "l"(v));
}

union F4U2 { float4 f4; unsigned long long u2[2]; };

// ---------------------------------------------------------------------------
// Fully fused kernel: one block per (b,h), 512 threads.
// Phase A (prep, in-smem): chunk totals -> suffix scan -> active start ->
//   per-timestep decay weights ws[].
// Phase B: accumulate out[p,n] = sum_t ws[t]*X[t,p]*B[t,n] over active chunks
//   with register-prefetch double buffering and packed FFMA2.
// ---------------------------------------------------------------------------
__global__ void __launch_bounds__(512)
fused_mamba_kernel(const float* __restrict__ X,
                   const float* __restrict__ A,
                   const float* __restrict__ B,
                   float* __restrict__ out) {
    __shared__ float xs[LCHUNK][PDIM];     // w-scaled X tile [l][p]   (16KB)
    __shared__ float bs[LCHUNK][NDIM];     // B tile [l][n]            (16KB)
    __shared__ float ws[NCHUNK * LCHUNK];  // per-t weights            (16KB)
    __shared__ float Tj[NCHUNK];
    __shared__ float Uj[NCHUNK];
    __shared__ int   s_start;

    const int bh   = blockIdx.x;
    const int b    = bh >> 4;
    const int h    = bh & 15;
    const int tid  = threadIdx.x;
    const int lane = tid & 31;
    const int warp = tid >> 5;

    const float* Ab = A + (long)b * SDIM * HDIM + h;

    if (tid == 0) s_start = NCHUNK - 1;

    // ---- Phase A1: chunk totals (8 threads per chunk, 8 consecutive t) ----
    {
        const int j = tid >> 3, q = tid & 7;
        const int t0 = j * LCHUNK + q * 8;
        float s = 0.0f;
        #pragma unroll
        for (int i = 0; i < 8; i++) s += Ab[(t0 + i) * HDIM];
        s += __shfl_down_sync(0xffffffffu, s, 4);
        s += __shfl_down_sync(0xffffffffu, s, 2);
        s += __shfl_down_sync(0xffffffffu, s, 1);
        if (q == 0) Tj[j] = s;
    }
    __syncthreads();

    // ---- Phase A2: suffix sums via reversed inclusive warp scan (warp 0) --
    if (warp == 0) {
        const int r0 = 2 * lane, r1 = 2 * lane + 1;
        const float a0 = Tj[63 - r0];
        const float a1 = Tj[63 - r1];
        float sc = a0 + a1;
        #pragma unroll
        for (int d = 1; d < 32; d <<= 1) {
            float o = __shfl_up_sync(0xffffffffu, sc, d);
            if (lane >= d) sc += o;
        }
        Uj[63 - r0] = (sc - a1) - a0;
        Uj[63 - r1] = sc - a1;
    }
    __syncthreads();

    if (tid < NCHUNK && Uj[tid] > -THRESH) atomicMin(&s_start, tid);
    __syncthreads();
    const int start = s_start;

    // ---- Phase A3: weights for active chunks (one warp per chunk) ---------
    for (int j = start + warp; j < NCHUNK; j += 16) {
        const int t0 = j * LCHUNK;
        const float a0 = Ab[(t0 + 2 * lane)     * HDIM];
        const float a1 = Ab[(t0 + 2 * lane + 1) * HDIM];
        float sc = a0 + a1;
        #pragma unroll
        for (int d = 1; d < 32; d <<= 1) {
            float o = __shfl_up_sync(0xffffffffu, sc, d);
            if (lane >= d) sc += o;
        }
        const float base = Uj[j] + Tj[j];
        float2 wv;
        wv.x = __expf(base - (sc - a1));
        wv.y = __expf(base - sc);
        ((float2*)(ws + t0))[lane] = wv;
    }
    __syncthreads();

    // ---- Phase B: accumulate over active chunks ---------------------------
    const float4* X4 = (const float4*)X;
    const float4* B4 = (const float4*)B;

    const int p0 = warp * 4;   // 4 p-values per thread
    const int n0 = lane * 2;   // 2 n-values per thread

    // acc[pi][ni]: packed pair (out[p0+2pi, n0+ni], out[p0+2pi+1, n0+ni])
    unsigned long long acc[2][2] = {{0ull, 0ull}, {0ull, 0ull}};

    float4 xr[2], br[2];

    // Preload chunk `start` (each thread: 2 x-float4 + 2 b-float4)
    #pragma unroll
    for (int k = 0; k < 2; k++) {
        const int idx = k * 512 + tid;           // 0..1023
        const int row = idx >> 4;
        const int col = idx & 15;
        const int base = ((b * SDIM + start * LCHUNK + row) * HDIM + h) * 16 + col;
        xr[k] = X4[base];
        br[k] = B4[base];
    }

    for (int j = start; j < NCHUNK; j++) {
        // Stage regs -> shared, scaling X by weight (weights from smem)
        #pragma unroll
        for (int k = 0; k < 2; k++) {
            const int idx = k * 512 + tid;
            const int row = idx >> 4;
            const int col = idx & 15;
            const float w = ws[j * LCHUNK + row];
            float4 xv = xr[k];
            xv.x *= w; xv.y *= w; xv.z *= w; xv.w *= w;
            *(float4*)&xs[row][col * 4] = xv;
            *(float4*)&bs[row][col * 4] = br[k];
        }
        __syncthreads();

        // Prefetch next chunk while computing this one
        if (j + 1 < NCHUNK) {
            #pragma unroll
            for (int k = 0; k < 2; k++) {
                const int idx = k * 512 + tid;
                const int row = idx >> 4;
                const int col = idx & 15;
                const int base = ((b * SDIM + (j + 1) * LCHUNK + row) * HDIM + h) * 16 + col;
                xr[k] = X4[base];
                br[k] = B4[base];
            }
        }

        // Rank-64 update: 8 outputs per thread
        #pragma unroll 4
        for (int l = 0; l < LCHUNK; l++) {
            F4U2 xa;
            xa.f4 = *(const float4*)&xs[l][p0];          // broadcast in warp
            const float2 bv = *(const float2*)&bs[l][n0]; // conflict-free
            const unsigned long long b0 = pack2(bv.x, bv.x);
            const unsigned long long b1 = pack2(bv.y, bv.y);
            ffma2(acc[0][0], xa.u2[0], b0);
            ffma2(acc[0][1], xa.u2[0], b1);
            ffma2(acc[1][0], xa.u2[1], b0);
            ffma2(acc[1][1], xa.u2[1], b1);
        }
        __syncthreads();
    }

    // ---- Write out[bh, p, n] ----------------------------------------------
    float2* out2 = (float2*)out + (long)bh * PDIM * (NDIM / 2);
    #pragma unroll
    for (int pi = 0; pi < 2; pi++) {
        float2 lo, hi;
        unpack2(acc[pi][0], lo.x, hi.x);
        unpack2(acc[pi][1], lo.y, hi.y);
        out2[(p0 + 2 * pi)     * 32 + lane] = lo;
        out2[(p0 + 2 * pi + 1) * 32 + lane] = hi;
    }
}

// ---------------------------------------------------------------------------
extern "C" void kernel_launch(void* const* d_in, const int* in_sizes, int n_in,
                              void* d_out, int out_size) {
    const float* X = (const float*)d_in[0];
    const float* A = (const float*)d_in[1];
    const float* B = (const float*)d_in[2];
    float* out = (float*)d_out;

    fused_mamba_kernel<<<NBH, 512>>>(X, A, B, out);
}

// round 6
// speedup vs baseline: 1.8636x; 1.6061x over previous
#include <cuda_runtime.h>
#include <cuda_bf16.h>

#define SDIM   4096
#define HDIM   16
#define PDIM   64
#define NDIM   64
#define LCHUNK 64
#define NCHUNK 64
#define NBH    128
#define THRESH 14.0f      // exp(-14)=8e-7; truncation ~1e-5 rel << 1e-3 budget
#define CAP    5          // chunk slots in smem per round
#define THREADS 256
#define WIN    512        // backward A-scan window (8 chunks)

// Dynamic smem layout (in floats):
//   xs slots : [CAP][64][64]   (w-scaled X tiles)
//   bs slots : [CAP][64][64]   (B tiles)
//   ws       : [SDIM]          (per-t decay weights)
#define XS_OFF 0
#define BS_OFF (CAP * 4096)
#define WS_OFF (2 * CAP * 4096)
#define SMEM_BYTES ((2 * CAP * 4096 + SDIM) * 4)

// Packed-f32 FMA helpers (sm_100+: fma.rn.f32x2)
__device__ __forceinline__ void ffma2(unsigned long long& d,
                                      unsigned long long a,
                                      unsigned long long b) {
    asm("fma.rn.f32x2 %0, %1, %2, %0;" : "+l"(d) : "l"(a), "l"(b));
}
__device__ __forceinline__ unsigned long long pack2(float lo, float hi) {
    unsigned long long r;
    asm("mov.b64 %0, {%1, %2};" : "=l"(r) : "f"(lo), "f"(hi));
    return r;
}
__device__ __forceinline__ void unpack2(unsigned long long v, float& lo, float& hi) {
    asm("mov.b64 {%0, %1}, %2;" : "=f"(lo), "=f"(hi) : "l"(v));
}
__device__ __forceinline__ void cp16(float* smem_dst, const float4* gmem_src) {
    unsigned sptr = (unsigned)__cvta_generic_to_shared(smem_dst);
    asm volatile("cp.async.cg.shared.global [%0], [%1], 16;"
                 :: "r"(sptr), "l"(gmem_src) : "memory");
}

union F4U2 { float4 f4; unsigned long long u2[2]; };

__global__ void __launch_bounds__(THREADS)
fused_mamba_kernel(const float* __restrict__ X,
                   const float* __restrict__ A,
                   const float* __restrict__ B,
                   float* __restrict__ out) {
    extern __shared__ float sm[];
    float* ws = sm + WS_OFF;

    __shared__ float warpsum[8];
    __shared__ int   s_start;

    const int bh   = blockIdx.x;
    const int b    = bh >> 4;
    const int h    = bh & 15;
    const int tid  = threadIdx.x;
    const int lane = tid & 31;
    const int warp = tid >> 5;

    const float* Ab = A + (long)b * SDIM * HDIM + h;

    if (tid == 0) s_start = NCHUNK - 1;   // chunk 63 always active (suffix=0)
    __syncthreads();

    // ---- Phase A: backward windowed scan of A (usually ONE window) --------
    float suffixBeyond = 0.0f;            // uniform across block
    int winEnd = SDIM;
    for (;;) {
        const int winStart = winEnd - WIN;
        // Each thread owns t = winStart + 2*tid, +1
        const float a0 = Ab[(winStart + 2 * tid)     * HDIM];
        const float a1 = Ab[(winStart + 2 * tid + 1) * HDIM];
        float sc = a0 + a1;
        #pragma unroll
        for (int d = 1; d < 32; d <<= 1) {
            float o = __shfl_up_sync(0xffffffffu, sc, d);
            if (lane >= d) sc += o;
        }
        if (lane == 31) warpsum[warp] = sc;
        __syncthreads();
        // Warp 0 scans the 8 warp sums (inclusive)
        if (warp == 0 && lane < 8) {
            float v = warpsum[lane];
            #pragma unroll
            for (int d = 1; d < 8; d <<= 1) {
                float o = __shfl_up_sync(0x000000ffu, v, d);
                if (lane >= d) v += o;
            }
            warpsum[lane] = v;
        }
        __syncthreads();
        const float off   = (warp > 0) ? warpsum[warp - 1] : 0.0f;
        const float total = warpsum[7];
        const float cs1 = sc + off;        // inclusive cumsum through t1
        const float cs0 = cs1 - a1;
        // weights: w(t) = exp(sum of A over t' > t)
        float2 wv;
        wv.x = __expf(total - cs0 + suffixBeyond);
        wv.y = __expf(total - cs1 + suffixBeyond);
        ((float2*)(ws + winStart))[tid] = wv;
        // chunk-boundary threads test activity (t1 is last t of its chunk)
        if (lane == 31) {
            const int t1 = winStart + 2 * tid + 1;   // (t1&63)==63 here
            const float Uj = total - cs1 + suffixBeyond;  // suffix AFTER chunk
            if (Uj > -THRESH) atomicMin(&s_start, t1 >> 6);
        }
        const float newSuffix = suffixBeyond + total;
        __syncthreads();                   // protect warpsum reuse
        if (winStart == 0 || newSuffix < -THRESH) break;
        suffixBeyond = newSuffix;
        winEnd = winStart;
    }
    const int start = s_start;             // set via atomicMin; post-sync read
    __syncthreads();

    // ---- Phase B: bulk-load active chunks, scale, compute ------------------
    const float4* X4 = (const float4*)X;
    const float4* B4 = (const float4*)B;

    const int p0 = (tid >> 4) << 2;        // 0..60
    const int n0 = (tid & 15) << 2;        // 0..60

    unsigned long long acc[2][4];
    #pragma unroll
    for (int i = 0; i < 2; i++)
        #pragma unroll
        for (int n = 0; n < 4; n++) acc[i][n] = 0ull;

    for (int c0 = start; c0 < NCHUNK; c0 += CAP) {
        const int nc = min(CAP, NCHUNK - c0);

        // Issue ALL loads for this round (cp.async, 16B each)
        for (int c = 0; c < nc; c++) {
            const long tbase = (long)(b * SDIM + (c0 + c) * LCHUNK) * HDIM + h;
            #pragma unroll
            for (int k = 0; k < 4; k++) {
                const int i   = k * THREADS + tid;     // 0..1023
                const int row = i >> 4;
                const int col = i & 15;
                const long g  = (tbase + (long)row * HDIM) * 16 + col;
                cp16(sm + XS_OFF + c * 4096 + row * 64 + col * 4, X4 + g);
                cp16(sm + BS_OFF + c * 4096 + row * 64 + col * 4, B4 + g);
            }
        }
        asm volatile("cp.async.commit_group;" ::: "memory");
        asm volatile("cp.async.wait_group 0;" ::: "memory");
        __syncthreads();

        // Scale xs rows by decay weight
        for (int c = 0; c < nc; c++) {
            float* xsl = sm + XS_OFF + c * 4096;
            const int tw = (c0 + c) * LCHUNK;
            #pragma unroll
            for (int k = 0; k < 4; k++) {
                const int i   = k * THREADS + tid;
                const int row = i >> 4;
                const int col = i & 15;
                float4 v = *(float4*)&xsl[row * 64 + col * 4];
                const float w = ws[tw + row];
                v.x *= w; v.y *= w; v.z *= w; v.w *= w;
                *(float4*)&xsl[row * 64 + col * 4] = v;
            }
        }
        __syncthreads();

        // Compute: rank-64 update per chunk, 4p x 4n per thread
        for (int c = 0; c < nc; c++) {
            const float* xsl = sm + XS_OFF + c * 4096;
            const float* bsl = sm + BS_OFF + c * 4096;
            #pragma unroll 4
            for (int l = 0; l < LCHUNK; l++) {
                F4U2 xa;
                xa.f4 = *(const float4*)&xsl[l * 64 + p0];
                const float4 bv = *(const float4*)&bsl[l * 64 + n0];
                const unsigned long long b0 = pack2(bv.x, bv.x);
                const unsigned long long b1 = pack2(bv.y, bv.y);
                const unsigned long long b2 = pack2(bv.z, bv.z);
                const unsigned long long b3 = pack2(bv.w, bv.w);
                ffma2(acc[0][0], xa.u2[0], b0);
                ffma2(acc[0][1], xa.u2[0], b1);
                ffma2(acc[0][2], xa.u2[0], b2);
                ffma2(acc[0][3], xa.u2[0], b3);
                ffma2(acc[1][0], xa.u2[1], b0);
                ffma2(acc[1][1], xa.u2[1], b1);
                ffma2(acc[1][2], xa.u2[1], b2);
                ffma2(acc[1][3], xa.u2[1], b3);
            }
        }
        if (c0 + CAP < NCHUNK) __syncthreads();   // smem reuse next round
    }

    // ---- Write out[bh, p, n] (float4 over n) -------------------------------
    float4* out4 = (float4*)out + (long)bh * PDIM * 16;
    #pragma unroll
    for (int pi = 0; pi < 2; pi++) {
        float4 vlo, vhi;
        unpack2(acc[pi][0], vlo.x, vhi.x);
        unpack2(acc[pi][1], vlo.y, vhi.y);
        unpack2(acc[pi][2], vlo.z, vhi.z);
        unpack2(acc[pi][3], vlo.w, vhi.w);
        out4[(p0 + 2 * pi)     * 16 + (n0 >> 2)] = vlo;
        out4[(p0 + 2 * pi + 1) * 16 + (n0 >> 2)] = vhi;
    }
}

// ---------------------------------------------------------------------------
extern "C" void kernel_launch(void* const* d_in, const int* in_sizes, int n_in,
                              void* d_out, int out_size) {
    const float* X = (const float*)d_in[0];
    const float* A = (const float*)d_in[1];
    const float* B = (const float*)d_in[2];
    float* out = (float*)d_out;

    cudaFuncSetAttribute(fused_mamba_kernel,
                         cudaFuncAttributeMaxDynamicSharedMemorySize,
                         SMEM_BYTES);
    fused_mamba_kernel<<<NBH, THREADS, SMEM_BYTES>>>(X, A, B, out);
}